// round 1
// baseline (speedup 1.0000x reference)
#include <cuda_runtime.h>
#include <math.h>

#define BATCH 4
#define C64   64
#define CR    32
#define HIMG  96
#define SIMG  48
#define NQ    9216      // 96*96 queries
#define NL    2304      // 48*48 keys
#define DK    288       // 32*3*3
#define DV    576       // 64*3*3
#define OHW   191
#define SCALEF 10.0f
#define EPSF   1e-4f

// ---------------- scratch (device globals; no allocation allowed) ----------------
__device__ float g_match[(size_t)BATCH * CR  * NQ];   //  4.7 MB
__device__ float g_embed[(size_t)BATCH * C64 * NL];   //  2.4 MB
__device__ float g_ref  [(size_t)BATCH * CR  * NL];   //  1.2 MB
__device__ float g_Q    [(size_t)BATCH * NQ  * DK];   // 42.5 MB   [b][q][d]
__device__ float g_Km   [(size_t)BATCH * NL  * DK];   // 10.6 MB   [b][l][d]  (normalized)
__device__ float g_V    [(size_t)BATCH * DV  * NL];   // 21.2 MB   [b][dv][l]
__device__ float g_invn [(size_t)BATCH * NL];
__device__ float g_S    [(size_t)BATCH * NQ  * NL];   // 340 MB    [b][q][l]
__device__ float g_O    [(size_t)BATCH * NQ  * DV];   // 85 MB     [b][q][dv]

// ---------------- 1x1 conv + PReLU ----------------
template<int CINT, int COUT>
__global__ void __launch_bounds__(256)
conv1x1_prelu(const float* __restrict__ in, const float* __restrict__ w,
              const float* __restrict__ bias, const float* __restrict__ a,
              float* __restrict__ out, int HW) {
    __shared__ float ws[COUT * CINT];
    for (int i = threadIdx.x; i < COUT * CINT; i += blockDim.x) ws[i] = w[i];
    __syncthreads();
    const float alpha = a[0];
    int idx = blockIdx.x * blockDim.x + threadIdx.x;     // b*HW + p (grid exact)
    int b = idx / HW, p = idx - b * HW;
    const float* inp = in + (size_t)b * CINT * HW + p;
    float acc[COUT];
#pragma unroll
    for (int o = 0; o < COUT; o++) acc[o] = bias[o];
    for (int c = 0; c < CINT; c++) {
        float v = inp[(size_t)c * HW];
#pragma unroll
        for (int o = 0; o < COUT; o++) acc[o] = fmaf(ws[o * CINT + c], v, acc[o]);
    }
    float* op = out + (size_t)b * COUT * HW + p;
#pragma unroll
    for (int o = 0; o < COUT; o++) {
        float v = acc[o];
        op[(size_t)o * HW] = (v >= 0.f) ? v : alpha * v;
    }
}

// ---------------- Q = im2col(match), zero-padded ----------------
__global__ void im2col_q() {
    size_t idx = (size_t)blockIdx.x * 256 + threadIdx.x;   // grid exact: 4*9216*288
    int d = (int)(idx % DK);
    int q = (int)((idx / DK) % NQ);
    int b = (int)(idx / ((size_t)DK * NQ));
    int c = d / 9, kk = d % 9, ky = kk / 3, kx = kk % 3;
    int y = q / HIMG, x = q % HIMG;
    int yy = y + ky - 1, xx = x + kx - 1;
    float v = 0.f;
    if (yy >= 0 && yy < HIMG && xx >= 0 && xx < HIMG)
        v = g_match[(((size_t)b * CR + c) * HIMG + yy) * HIMG + xx];
    g_Q[idx] = v;
}

// ---------------- per-key inverse patch norms ----------------
__global__ void key_inv_norms() {
    int idx = blockIdx.x * 256 + threadIdx.x;   // 4*2304 exact
    int l = idx % NL, b = idx / NL;
    int ly = l / SIMG, lx = l % SIMG;
    const float* rb = g_ref + (size_t)b * CR * NL;
    float ss = 0.f;
    for (int c = 0; c < CR; c++)
        for (int ky = 0; ky < 3; ky++) {
            int yy = ly + ky - 1;
            if (yy < 0 || yy >= SIMG) continue;
            for (int kx = 0; kx < 3; kx++) {
                int xx = lx + kx - 1;
                if (xx < 0 || xx >= SIMG) continue;
                float v = rb[((size_t)c * SIMG + yy) * SIMG + xx];
                ss += v * v;
            }
        }
    g_invn[idx] = 1.f / fmaxf(sqrtf(ss), EPSF);
}

// ---------------- K matrix = normalized ref patches ----------------
__global__ void build_km() {
    size_t idx = (size_t)blockIdx.x * 256 + threadIdx.x;   // 4*2304*288 exact
    int d = (int)(idx % DK);
    int l = (int)((idx / DK) % NL);
    int b = (int)(idx / ((size_t)DK * NL));
    int c = d / 9, kk = d % 9, ky = kk / 3, kx = kk % 3;
    int ly = l / SIMG, lx = l % SIMG;
    int yy = ly + ky - 1, xx = lx + kx - 1;
    float v = 0.f;
    if (yy >= 0 && yy < SIMG && xx >= 0 && xx < SIMG)
        v = g_ref[(((size_t)b * CR + c) * SIMG + yy) * SIMG + xx];
    g_Km[idx] = v * g_invn[b * NL + l];
}

// ---------------- V matrix (transposed: [b][dv][l]) = embed patches ----------------
__global__ void build_v() {
    size_t idx = (size_t)blockIdx.x * 256 + threadIdx.x;   // 4*576*2304 exact
    int l  = (int)(idx % NL);
    int dv = (int)((idx / NL) % DV);
    int b  = (int)(idx / ((size_t)NL * DV));
    int c = dv / 9, kk = dv % 9, ky = kk / 3, kx = kk % 3;
    int ly = l / SIMG, lx = l % SIMG;
    int yy = ly + ky - 1, xx = lx + kx - 1;
    float v = 0.f;
    if (yy >= 0 && yy < SIMG && xx >= 0 && xx < SIMG)
        v = g_embed[(((size_t)b * C64 + c) * SIMG + yy) * SIMG + xx];
    g_V[idx] = v;
}

// ---------------- C[M,N] = alpha * A[M,K] * B[N,K]^T  (batched via blockIdx.z) ----------------
__global__ void __launch_bounds__(256)
gemm_nt(const float* __restrict__ A, const float* __restrict__ B, float* __restrict__ C,
        int M, int N, int K, float alpha, size_t sA, size_t sB, size_t sC) {
    __shared__ float As[8][128];
    __shared__ float Bs[8][128];
    const float* Ab = A + (size_t)blockIdx.z * sA;
    const float* Bb = B + (size_t)blockIdx.z * sB;
    float* Cb = C + (size_t)blockIdx.z * sC;
    const int m0 = blockIdx.y * 128;
    const int n0 = blockIdx.x * 128;
    const int tid = threadIdx.x;
    const int tm = tid >> 4;          // 0..15
    const int tn = tid & 15;          // 0..15
    const int lr = tid >> 1;          // 0..127
    const int lc = (tid & 1) << 2;    // 0 or 4

    float acc[8][8];
#pragma unroll
    for (int i = 0; i < 8; i++)
#pragma unroll
        for (int j = 0; j < 8; j++) acc[i][j] = 0.f;

    const float* aptr = Ab + (size_t)(m0 + lr) * K + lc;   // M always mult of 128
    const int bn = n0 + lr;
    const float* bptr = Bb + (size_t)(bn < N ? bn : 0) * K + lc;
    const bool bvalid = (bn < N);

    for (int k0 = 0; k0 < K; k0 += 8) {
        float4 av = *(const float4*)(aptr + k0);
        float4 bv = make_float4(0.f, 0.f, 0.f, 0.f);
        if (bvalid) bv = *(const float4*)(bptr + k0);
        __syncthreads();
        As[lc + 0][lr] = av.x; As[lc + 1][lr] = av.y; As[lc + 2][lr] = av.z; As[lc + 3][lr] = av.w;
        Bs[lc + 0][lr] = bv.x; Bs[lc + 1][lr] = bv.y; Bs[lc + 2][lr] = bv.z; Bs[lc + 3][lr] = bv.w;
        __syncthreads();
#pragma unroll
        for (int kk = 0; kk < 8; kk++) {
            float ar[8], br[8];
            *(float4*)(ar)     = *(const float4*)(&As[kk][tm * 8]);
            *(float4*)(ar + 4) = *(const float4*)(&As[kk][tm * 8 + 4]);
            *(float4*)(br)     = *(const float4*)(&Bs[kk][tn * 8]);
            *(float4*)(br + 4) = *(const float4*)(&Bs[kk][tn * 8 + 4]);
#pragma unroll
            for (int i = 0; i < 8; i++)
#pragma unroll
                for (int j = 0; j < 8; j++)
                    acc[i][j] = fmaf(ar[i], br[j], acc[i][j]);
        }
    }
#pragma unroll
    for (int i = 0; i < 8; i++) {
        int m = m0 + tm * 8 + i;
        float* crow = Cb + (size_t)m * N;
#pragma unroll
        for (int j = 0; j < 8; j += 4) {
            int n = n0 + tn * 8 + j;
            if (n < N) {
                float4 v = make_float4(acc[i][j] * alpha, acc[i][j + 1] * alpha,
                                       acc[i][j + 2] * alpha, acc[i][j + 3] * alpha);
                *(float4*)(crow + n) = v;
            }
        }
    }
}

// ---------------- row softmax over 2304 keys (in place on g_S) ----------------
__global__ void __launch_bounds__(256)
softmax_rows() {
    float* p = g_S + (size_t)blockIdx.x * NL;   // 36864 rows
    const int t = threadIdx.x;
    float v[9];
    float m = -1e30f;
#pragma unroll
    for (int i = 0; i < 9; i++) { v[i] = p[t + i * 256]; m = fmaxf(m, v[i]); }
    __shared__ float red[256];
    red[t] = m; __syncthreads();
    for (int s = 128; s > 0; s >>= 1) { if (t < s) red[t] = fmaxf(red[t], red[t + s]); __syncthreads(); }
    m = red[0];
    __syncthreads();
    float sum = 0.f;
#pragma unroll
    for (int i = 0; i < 9; i++) { v[i] = expf(v[i] - m); sum += v[i]; }
    red[t] = sum; __syncthreads();
    for (int s = 128; s > 0; s >>= 1) { if (t < s) red[t] += red[t + s]; __syncthreads(); }
    float inv = 1.f / red[0];
#pragma unroll
    for (int i = 0; i < 9; i++) p[t + i * 256] = v[i] * inv;
}

// ---------------- gather epilogue (stride-2 transposed conv as gather) ----------------
__global__ void epilogue(float* __restrict__ out) {
    size_t idx = (size_t)blockIdx.x * 256 + threadIdx.x;   // 4*64*191*191 exact
    int X = (int)(idx % OHW);
    int Y = (int)((idx / OHW) % OHW);
    int c = (int)((idx / ((size_t)OHW * OHW)) % C64);
    int b = (int)(idx / ((size_t)OHW * OHW * C64));

    int ys[2], kys[2], ny;
    if (Y & 1) { ny = 2; ys[0] = (Y - 1) >> 1; kys[0] = 2; ys[1] = (Y + 1) >> 1; kys[1] = 0; }
    else       { ny = 1; ys[0] = Y >> 1;       kys[0] = 1; }
    int xs[2], kxs[2], nx;
    if (X & 1) { nx = 2; xs[0] = (X - 1) >> 1; kxs[0] = 2; xs[1] = (X + 1) >> 1; kxs[1] = 0; }
    else       { nx = 1; xs[0] = X >> 1;       kxs[0] = 1; }

    const float* Ob = g_O + (size_t)b * NQ * DV;
    float s = 0.f;
    for (int iy = 0; iy < ny; iy++)
        for (int ix = 0; ix < nx; ix++) {
            int q = ys[iy] * HIMG + xs[ix];
            s += Ob[(size_t)q * DV + c * 9 + kys[iy] * 3 + kxs[ix]];
        }
    out[idx] = s * (1.0f / 6.0f);
}

// ---------------- launch ----------------
extern "C" void kernel_launch(void* const* d_in, const int* in_sizes, int n_in,
                              void* d_out, int out_size) {
    const float* input = (const float*)d_in[0];
    const float* small = (const float*)d_in[1];
    const float* w1 = (const float*)d_in[2];
    const float* b1 = (const float*)d_in[3];
    const float* a1 = (const float*)d_in[4];
    const float* w2 = (const float*)d_in[5];
    const float* b2 = (const float*)d_in[6];
    const float* a2 = (const float*)d_in[7];
    const float* wa = (const float*)d_in[8];
    const float* ba = (const float*)d_in[9];
    const float* aa = (const float*)d_in[10];
    float* out = (float*)d_out;

    float *p_match, *p_embed, *p_ref, *p_Q, *p_Km, *p_V, *p_S, *p_O;
    cudaGetSymbolAddress((void**)&p_match, g_match);
    cudaGetSymbolAddress((void**)&p_embed, g_embed);
    cudaGetSymbolAddress((void**)&p_ref,   g_ref);
    cudaGetSymbolAddress((void**)&p_Q,     g_Q);
    cudaGetSymbolAddress((void**)&p_Km,    g_Km);
    cudaGetSymbolAddress((void**)&p_V,     g_V);
    cudaGetSymbolAddress((void**)&p_S,     g_S);
    cudaGetSymbolAddress((void**)&p_O,     g_O);

    // feature maps
    conv1x1_prelu<C64, CR><<<144, 256>>>(input, w1, b1, a1, p_match, NQ);   // match_input
    conv1x1_prelu<C64, C64><<<36, 256>>>(small, wa, ba, aa, p_embed, NL);   // embed_w
    conv1x1_prelu<C64, CR><<<36, 256>>>(small, w2, b2, a2, p_ref, NL);      // ref

    // Q / K / V materialization
    im2col_q<<<41472, 256>>>();
    key_inv_norms<<<36, 256>>>();
    build_km<<<10368, 256>>>();
    build_v<<<20736, 256>>>();

    // S = 10 * Q K^T
    gemm_nt<<<dim3(18, 72, BATCH), 256>>>(p_Q, p_Km, p_S, NQ, NL, DK, SCALEF,
                                          (size_t)NQ * DK, (size_t)NL * DK, (size_t)NQ * NL);
    // softmax over keys
    softmax_rows<<<BATCH * NQ, 256>>>();
    // O = P V
    gemm_nt<<<dim3(5, 72, BATCH), 256>>>(p_S, p_V, p_O, NQ, DV, NL, 1.0f,
                                         (size_t)NQ * NL, (size_t)DV * NL, (size_t)NQ * DV);
    // scatter/gather into [4,64,191,191] with /6
    epilogue<<<36481, 256>>>(out);
}

// round 2
// speedup vs baseline: 3.1711x; 3.1711x over previous
#include <cuda_runtime.h>
#include <cstdint>
#include <math.h>

#define BATCH 4
#define C64   64
#define CR    32
#define HIMG  96
#define SIMG  48
#define NQ    9216      // 96*96 queries
#define NL    2304      // 48*48 keys
#define DK    288       // 32*3*3
#define DV    576       // 64*3*3
#define OHW   191
#define SCALEF 10.0f
#define EPSF   1e-4f

// ---------------- scratch (device globals; no allocation allowed) ----------------
__device__ float g_match[(size_t)BATCH * CR  * NQ];
__device__ float g_embed[(size_t)BATCH * C64 * NL];
__device__ float g_ref  [(size_t)BATCH * CR  * NL];
__device__ float g_Q    [(size_t)BATCH * NQ  * DK];   // tf32-rounded
__device__ float g_Km   [(size_t)BATCH * NL  * DK];   // tf32-rounded, normalized
__device__ float g_V    [(size_t)BATCH * DV  * NL];   // tf32-rounded
__device__ float g_invn [(size_t)BATCH * NL];
__device__ float g_S    [(size_t)BATCH * NQ  * NL];   // logits fp32, then softmax (tf32-rounded)
__device__ float g_O    [(size_t)BATCH * NQ  * DV];

__device__ __forceinline__ float tf32r(float x) {
    uint32_t u;
    asm("cvt.rna.tf32.f32 %0, %1;" : "=r"(u) : "f"(x));
    return __uint_as_float(u);
}

// ---------------- 1x1 conv + PReLU ----------------
template<int CINT, int COUT>
__global__ void __launch_bounds__(256)
conv1x1_prelu(const float* __restrict__ in, const float* __restrict__ w,
              const float* __restrict__ bias, const float* __restrict__ a,
              float* __restrict__ out, int HW) {
    __shared__ float ws[COUT * CINT];
    for (int i = threadIdx.x; i < COUT * CINT; i += blockDim.x) ws[i] = w[i];
    __syncthreads();
    const float alpha = a[0];
    int idx = blockIdx.x * blockDim.x + threadIdx.x;
    int b = idx / HW, p = idx - b * HW;
    const float* inp = in + (size_t)b * CINT * HW + p;
    float acc[COUT];
#pragma unroll
    for (int o = 0; o < COUT; o++) acc[o] = bias[o];
    for (int c = 0; c < CINT; c++) {
        float v = inp[(size_t)c * HW];
#pragma unroll
        for (int o = 0; o < COUT; o++) acc[o] = fmaf(ws[o * CINT + c], v, acc[o]);
    }
    float* op = out + (size_t)b * COUT * HW + p;
#pragma unroll
    for (int o = 0; o < COUT; o++) {
        float v = acc[o];
        op[(size_t)o * HW] = (v >= 0.f) ? v : alpha * v;
    }
}

// ---------------- Q = im2col(match), zero-padded, tf32-rounded ----------------
__global__ void im2col_q() {
    size_t idx = (size_t)blockIdx.x * 256 + threadIdx.x;
    int d = (int)(idx % DK);
    int q = (int)((idx / DK) % NQ);
    int b = (int)(idx / ((size_t)DK * NQ));
    int c = d / 9, kk = d % 9, ky = kk / 3, kx = kk % 3;
    int y = q / HIMG, x = q % HIMG;
    int yy = y + ky - 1, xx = x + kx - 1;
    float v = 0.f;
    if (yy >= 0 && yy < HIMG && xx >= 0 && xx < HIMG)
        v = g_match[(((size_t)b * CR + c) * HIMG + yy) * HIMG + xx];
    g_Q[idx] = tf32r(v);
}

// ---------------- per-key inverse patch norms ----------------
__global__ void key_inv_norms() {
    int idx = blockIdx.x * 256 + threadIdx.x;
    int l = idx % NL, b = idx / NL;
    int ly = l / SIMG, lx = l % SIMG;
    const float* rb = g_ref + (size_t)b * CR * NL;
    float ss = 0.f;
    for (int c = 0; c < CR; c++)
        for (int ky = 0; ky < 3; ky++) {
            int yy = ly + ky - 1;
            if (yy < 0 || yy >= SIMG) continue;
            for (int kx = 0; kx < 3; kx++) {
                int xx = lx + kx - 1;
                if (xx < 0 || xx >= SIMG) continue;
                float v = rb[((size_t)c * SIMG + yy) * SIMG + xx];
                ss += v * v;
            }
        }
    g_invn[idx] = 1.f / fmaxf(sqrtf(ss), EPSF);
}

// ---------------- K matrix = normalized ref patches, tf32-rounded ----------------
__global__ void build_km() {
    size_t idx = (size_t)blockIdx.x * 256 + threadIdx.x;
    int d = (int)(idx % DK);
    int l = (int)((idx / DK) % NL);
    int b = (int)(idx / ((size_t)DK * NL));
    int c = d / 9, kk = d % 9, ky = kk / 3, kx = kk % 3;
    int ly = l / SIMG, lx = l % SIMG;
    int yy = ly + ky - 1, xx = lx + kx - 1;
    float v = 0.f;
    if (yy >= 0 && yy < SIMG && xx >= 0 && xx < SIMG)
        v = g_ref[(((size_t)b * CR + c) * SIMG + yy) * SIMG + xx];
    g_Km[idx] = tf32r(v * g_invn[b * NL + l]);
}

// ---------------- V matrix ([b][dv][l]) = embed patches, tf32-rounded ----------------
__global__ void build_v() {
    size_t idx = (size_t)blockIdx.x * 256 + threadIdx.x;
    int l  = (int)(idx % NL);
    int dv = (int)((idx / NL) % DV);
    int b  = (int)(idx / ((size_t)NL * DV));
    int c = dv / 9, kk = dv % 9, ky = kk / 3, kx = kk % 3;
    int ly = l / SIMG, lx = l % SIMG;
    int yy = ly + ky - 1, xx = lx + kx - 1;
    float v = 0.f;
    if (yy >= 0 && yy < SIMG && xx >= 0 && xx < SIMG)
        v = g_embed[(((size_t)b * C64 + c) * SIMG + yy) * SIMG + xx];
    g_V[idx] = tf32r(v);
}

// ============ TF32 tensor-core GEMM: C[M,N] = alpha * A[M,K] * B[N,K]^T ============
// 128x128 block, 8 warps (4m x 2n) each 32x64, K-tile 32, cp.async double buffer.
// Smem layout [row][36] padded: fragment LDS bank = (4*row + k) % 32, bijective
// over (g in 0..7, t in 0..3) -> conflict-free.

#define GT_STAGE_F 4608              // 128*36 floats per stage
#define GT_STAGE_B 18432             // bytes
#define GT_SMEM    (4 * GT_STAGE_B)  // A(2 stages) + B(2 stages) = 73728 B

__device__ __forceinline__ void mma_tf32(float c[4], const uint32_t a[4], const uint32_t b[2]) {
    asm volatile(
        "mma.sync.aligned.m16n8k8.row.col.f32.tf32.tf32.f32 "
        "{%0,%1,%2,%3}, {%4,%5,%6,%7}, {%8,%9}, {%0,%1,%2,%3};"
        : "+f"(c[0]), "+f"(c[1]), "+f"(c[2]), "+f"(c[3])
        : "r"(a[0]), "r"(a[1]), "r"(a[2]), "r"(a[3]),
          "r"(b[0]), "r"(b[1]));
}

__device__ __forceinline__ void cp16(uint32_t dst, const float* src, int srcsize) {
    asm volatile("cp.async.cg.shared.global [%0], [%1], 16, %2;"
                 :: "r"(dst), "l"(src), "r"(srcsize));
}

__global__ void __launch_bounds__(256, 2)
gemm_tc(const float* __restrict__ A, const float* __restrict__ B, float* __restrict__ C,
        int M, int N, int K, float alpha, size_t sA, size_t sB, size_t sC) {
    extern __shared__ float sm[];
    const int tid  = threadIdx.x;
    const int warp = tid >> 5, lane = tid & 31;
    const int g = lane >> 2, t = lane & 3;
    const int wm = warp & 3, wn = warp >> 2;
    const int m0 = blockIdx.y * 128, n0 = blockIdx.x * 128;
    const float* Ab = A + (size_t)blockIdx.z * sA;
    const float* Bb = B + (size_t)blockIdx.z * sB;
    float* Cb = C + (size_t)blockIdx.z * sC;

    uint32_t smem_u = (uint32_t)__cvta_generic_to_shared(sm);
    const uint32_t a_base = smem_u;
    const uint32_t b_base = smem_u + 2 * GT_STAGE_B;

    // loader: each thread moves 4 float4 of A and 4 float4 of B per K-tile
    const int lm0 = tid >> 3;        // row for i=0 (0..31), +32 per i
    const int lkq = tid & 7;         // float4 index within row

    float acc[2][8][4];
#pragma unroll
    for (int i = 0; i < 2; i++)
#pragma unroll
        for (int j = 0; j < 8; j++)
#pragma unroll
            for (int r = 0; r < 4; r++) acc[i][j][r] = 0.f;

    auto ld_stage = [&](int k0, int s) {
#pragma unroll
        for (int i = 0; i < 4; i++) {
            int m = lm0 + 32 * i;
            uint32_t off = (uint32_t)((m * 36 + lkq * 4) * 4) + (uint32_t)s * GT_STAGE_B;
            const float* ga = Ab + (size_t)(m0 + m) * K + k0 + lkq * 4;
            cp16(a_base + off, ga, 16);
            int n = n0 + m;
            int nc = (n < N) ? n : (N - 1);
            const float* gb = Bb + (size_t)nc * K + k0 + lkq * 4;
            cp16(b_base + off, gb, (n < N) ? 16 : 0);
        }
        asm volatile("cp.async.commit_group;" ::: "memory");
    };

    ld_stage(0, 0);
    const int nk = K >> 5;

    for (int kt = 0; kt < nk; kt++) {
        asm volatile("cp.async.wait_group 0;" ::: "memory");
        __syncthreads();
        if (kt + 1 < nk) ld_stage((kt + 1) << 5, (kt + 1) & 1);

        const float* Ap = sm + (kt & 1) * GT_STAGE_F;
        const float* Bp = sm + 2 * GT_STAGE_F + (kt & 1) * GT_STAGE_F;
#pragma unroll
        for (int ks = 0; ks < 4; ks++) {
            const int kb = ks * 8;
            uint32_t afr[2][4], bfr[8][2];
#pragma unroll
            for (int mi = 0; mi < 2; mi++) {
                int r = wm * 32 + mi * 16 + g;
                afr[mi][0] = __float_as_uint(Ap[r * 36 + kb + t]);
                afr[mi][1] = __float_as_uint(Ap[(r + 8) * 36 + kb + t]);
                afr[mi][2] = __float_as_uint(Ap[r * 36 + kb + t + 4]);
                afr[mi][3] = __float_as_uint(Ap[(r + 8) * 36 + kb + t + 4]);
            }
#pragma unroll
            for (int ni = 0; ni < 8; ni++) {
                int r = wn * 64 + ni * 8 + g;
                bfr[ni][0] = __float_as_uint(Bp[r * 36 + kb + t]);
                bfr[ni][1] = __float_as_uint(Bp[r * 36 + kb + t + 4]);
            }
#pragma unroll
            for (int mi = 0; mi < 2; mi++)
#pragma unroll
                for (int ni = 0; ni < 8; ni++)
                    mma_tf32(acc[mi][ni], afr[mi], bfr[ni]);
        }
    }

    // epilogue
#pragma unroll
    for (int mi = 0; mi < 2; mi++) {
        int row0 = m0 + wm * 32 + mi * 16 + g;
#pragma unroll
        for (int ni = 0; ni < 8; ni++) {
            int col = n0 + wn * 64 + ni * 8 + 2 * t;
            if (col < N) {
                float2 v0 = make_float2(acc[mi][ni][0] * alpha, acc[mi][ni][1] * alpha);
                *(float2*)(Cb + (size_t)row0 * N + col) = v0;
                float2 v1 = make_float2(acc[mi][ni][2] * alpha, acc[mi][ni][3] * alpha);
                *(float2*)(Cb + (size_t)(row0 + 8) * N + col) = v1;
            }
        }
    }
}

// ---------------- row softmax over 2304 keys (in place on g_S), tf32-rounded out ----------------
__global__ void __launch_bounds__(256)
softmax_rows() {
    float* p = g_S + (size_t)blockIdx.x * NL;
    const int t = threadIdx.x;
    float v[9];
    float m = -1e30f;
#pragma unroll
    for (int i = 0; i < 9; i++) { v[i] = p[t + i * 256]; m = fmaxf(m, v[i]); }
    __shared__ float red[256];
    red[t] = m; __syncthreads();
    for (int s = 128; s > 0; s >>= 1) { if (t < s) red[t] = fmaxf(red[t], red[t + s]); __syncthreads(); }
    m = red[0];
    __syncthreads();
    float sum = 0.f;
#pragma unroll
    for (int i = 0; i < 9; i++) { v[i] = expf(v[i] - m); sum += v[i]; }
    red[t] = sum; __syncthreads();
    for (int s = 128; s > 0; s >>= 1) { if (t < s) red[t] += red[t + s]; __syncthreads(); }
    float inv = 1.f / red[0];
#pragma unroll
    for (int i = 0; i < 9; i++) p[t + i * 256] = tf32r(v[i] * inv);
}

// ---------------- gather epilogue (stride-2 transposed conv as gather) ----------------
__global__ void epilogue(float* __restrict__ out) {
    size_t idx = (size_t)blockIdx.x * 256 + threadIdx.x;
    int X = (int)(idx % OHW);
    int Y = (int)((idx / OHW) % OHW);
    int c = (int)((idx / ((size_t)OHW * OHW)) % C64);
    int b = (int)(idx / ((size_t)OHW * OHW * C64));

    int ys[2], kys[2], ny;
    if (Y & 1) { ny = 2; ys[0] = (Y - 1) >> 1; kys[0] = 2; ys[1] = (Y + 1) >> 1; kys[1] = 0; }
    else       { ny = 1; ys[0] = Y >> 1;       kys[0] = 1; }
    int xs[2], kxs[2], nx;
    if (X & 1) { nx = 2; xs[0] = (X - 1) >> 1; kxs[0] = 2; xs[1] = (X + 1) >> 1; kxs[1] = 0; }
    else       { nx = 1; xs[0] = X >> 1;       kxs[0] = 1; }

    const float* Ob = g_O + (size_t)b * NQ * DV;
    float s = 0.f;
    for (int iy = 0; iy < ny; iy++)
        for (int ix = 0; ix < nx; ix++) {
            int q = ys[iy] * HIMG + xs[ix];
            s += Ob[(size_t)q * DV + c * 9 + kys[iy] * 3 + kxs[ix]];
        }
    out[idx] = s * (1.0f / 6.0f);
}

// ---------------- launch ----------------
extern "C" void kernel_launch(void* const* d_in, const int* in_sizes, int n_in,
                              void* d_out, int out_size) {
    const float* input = (const float*)d_in[0];
    const float* small = (const float*)d_in[1];
    const float* w1 = (const float*)d_in[2];
    const float* b1 = (const float*)d_in[3];
    const float* a1 = (const float*)d_in[4];
    const float* w2 = (const float*)d_in[5];
    const float* b2 = (const float*)d_in[6];
    const float* a2 = (const float*)d_in[7];
    const float* wa = (const float*)d_in[8];
    const float* ba = (const float*)d_in[9];
    const float* aa = (const float*)d_in[10];
    float* out = (float*)d_out;

    float *p_match, *p_embed, *p_ref, *p_Q, *p_Km, *p_V, *p_S, *p_O;
    cudaGetSymbolAddress((void**)&p_match, g_match);
    cudaGetSymbolAddress((void**)&p_embed, g_embed);
    cudaGetSymbolAddress((void**)&p_ref,   g_ref);
    cudaGetSymbolAddress((void**)&p_Q,     g_Q);
    cudaGetSymbolAddress((void**)&p_Km,    g_Km);
    cudaGetSymbolAddress((void**)&p_V,     g_V);
    cudaGetSymbolAddress((void**)&p_S,     g_S);
    cudaGetSymbolAddress((void**)&p_O,     g_O);

    cudaFuncSetAttribute(gemm_tc, cudaFuncAttributeMaxDynamicSharedMemorySize, GT_SMEM);

    // feature maps
    conv1x1_prelu<C64, CR><<<144, 256>>>(input, w1, b1, a1, p_match, NQ);
    conv1x1_prelu<C64, C64><<<36, 256>>>(small, wa, ba, aa, p_embed, NL);
    conv1x1_prelu<C64, CR><<<36, 256>>>(small, w2, b2, a2, p_ref, NL);

    // Q / K / V materialization (tf32-rounded)
    im2col_q<<<41472, 256>>>();
    key_inv_norms<<<36, 256>>>();
    build_km<<<10368, 256>>>();
    build_v<<<20736, 256>>>();

    // S = 10 * Q K^T   (tensor cores, tf32)
    gemm_tc<<<dim3(18, 72, BATCH), 256, GT_SMEM>>>(p_Q, p_Km, p_S, NQ, NL, DK, SCALEF,
                                                   (size_t)NQ * DK, (size_t)NL * DK, (size_t)NQ * NL);
    // softmax over keys (writes tf32-rounded P)
    softmax_rows<<<BATCH * NQ, 256>>>();
    // O = P V   (tensor cores, tf32)
    gemm_tc<<<dim3(5, 72, BATCH), 256, GT_SMEM>>>(p_S, p_V, p_O, NQ, DV, NL, 1.0f,
                                                  (size_t)NQ * NL, (size_t)DV * NL, (size_t)NQ * DV);
    // gather into [4,64,191,191] with /6
    epilogue<<<36481, 256>>>(out);
}

// round 4
// speedup vs baseline: 4.3901x; 1.3844x over previous
#include <cuda_runtime.h>
#include <cuda_fp16.h>
#include <cstdint>
#include <math.h>

#define BATCH 4
#define C64   64
#define CR    32
#define HIMG  96
#define SIMG  48
#define NQ    9216      // 96*96 queries
#define NL    2304      // 48*48 keys
#define DK    288       // 32*3*3
#define DV    576       // 64*3*3
#define OHW   191
#define SCALEF 10.0f
#define EPSF   1e-4f

// ---------------- scratch (device globals; no allocation allowed) ----------------
__device__ float  g_match[(size_t)BATCH * CR  * NQ];
__device__ float  g_embed[(size_t)BATCH * C64 * NL];
__device__ float  g_ref  [(size_t)BATCH * CR  * NL];
__device__ __half g_Q    [(size_t)BATCH * NQ  * DK];   // fp16
__device__ __half g_Km   [(size_t)BATCH * NL  * DK];   // fp16, normalized
__device__ __half g_V    [(size_t)BATCH * DV  * NL];   // fp16
__device__ float  g_invn [(size_t)BATCH * NL];
__device__ float  g_S    [(size_t)BATCH * NQ  * NL];   // fp32 logits
__device__ __half g_P    [(size_t)BATCH * NQ  * NL];   // fp16 softmax probs
__device__ float  g_O    [(size_t)BATCH * NQ  * DV];

// ==================== FP16 tensor-core GEMM ====================
// C[M,Nb] = alpha * A[M,K] * B[Nb,K]^T ; A,B fp16 row-major(K-contig), C fp32.
// 128x128 block, 8 warps (4m x 2n) of 32x64, K-tile 32 halves, cp.async 2-stage.
// Smem rows padded to 80B -> ldmatrix row banks 20r%32 all-distinct (conflict-free).

#define FG_STAGE 10240                  // 128 rows * 80 B
#define FG_SMEM  (4 * FG_STAGE)         // A x2 + B x2 = 40960 B

__device__ __forceinline__ void mma_f16(float c[4], const uint32_t a[4], const uint32_t b[2]) {
    asm volatile(
        "mma.sync.aligned.m16n8k16.row.col.f32.f16.f16.f32 "
        "{%0,%1,%2,%3}, {%4,%5,%6,%7}, {%8,%9}, {%0,%1,%2,%3};"
        : "+f"(c[0]), "+f"(c[1]), "+f"(c[2]), "+f"(c[3])
        : "r"(a[0]), "r"(a[1]), "r"(a[2]), "r"(a[3]), "r"(b[0]), "r"(b[1]));
}

#define LDSM_X4(r0, r1, r2, r3, addr) \
    asm volatile("ldmatrix.sync.aligned.m8n8.x4.shared.b16 {%0,%1,%2,%3}, [%4];" \
                 : "=r"(r0), "=r"(r1), "=r"(r2), "=r"(r3) : "r"(addr))

__device__ __forceinline__ void cp16(uint32_t dst, const void* src) {
    asm volatile("cp.async.cg.shared.global [%0], [%1], 16;" :: "r"(dst), "l"(src));
}

__global__ void __launch_bounds__(256, 2)
gemm_f16(const __half* __restrict__ A, const __half* __restrict__ B, float* __restrict__ C,
         int K, int Nb, float alpha, size_t sA, size_t sB, size_t sC) {
    __shared__ __align__(16) char smc[FG_SMEM];
    const uint32_t smem_u = (uint32_t)__cvta_generic_to_shared(smc);
    const uint32_t a_base = smem_u;
    const uint32_t b_base = smem_u + 2 * FG_STAGE;

    const int tid = threadIdx.x;
    const int warp = tid >> 5, lane = tid & 31;
    const int g = lane >> 2, t = lane & 3;
    const int wm = warp & 3, wn = warp >> 2;
    const int m0 = blockIdx.y * 128, n0 = blockIdx.x * 128;
    const __half* Ab = A + (size_t)blockIdx.z * sA;
    const __half* Bb = B + (size_t)blockIdx.z * sB;
    float* Cb = C + (size_t)blockIdx.z * sC;

    // loader indices: 512 16B-chunks per operand per stage, 2 per thread
    const int lrow = tid >> 2;       // 0..63 (+64 for i=1)
    const int lc16 = tid & 3;        // chunk within row

    float acc[2][8][4];
#pragma unroll
    for (int i = 0; i < 2; i++)
#pragma unroll
        for (int j = 0; j < 8; j++)
#pragma unroll
            for (int r = 0; r < 4; r++) acc[i][j][r] = 0.f;

    auto ld_stage = [&](int c, int s) {
        const int k0 = c << 5;
#pragma unroll
        for (int i = 0; i < 2; i++) {
            int row = lrow + 64 * i;
            uint32_t off = (uint32_t)s * FG_STAGE + (uint32_t)(row * 80 + lc16 * 16);
            cp16(a_base + off, Ab + (size_t)(m0 + row) * K + k0 + lc16 * 8);
            int n = n0 + row; n = (n < Nb) ? n : (Nb - 1);
            cp16(b_base + off, Bb + (size_t)n * K + k0 + lc16 * 8);
        }
        asm volatile("cp.async.commit_group;" ::: "memory");
    };

    const int nk = K >> 5;
    ld_stage(0, 0);

    // ldmatrix lane addressing (within current stage)
    const uint32_t a_row = (uint32_t)(wm * 32 + (lane & 15));     // + mi*16
    const uint32_t a_chk = (uint32_t)(lane >> 4);                 // + ks*2
    const uint32_t b_row = (uint32_t)(wn * 64 + (lane & 7) + ((lane & 16) >> 1)); // + 16*a
    const uint32_t b_chk = (uint32_t)((lane >> 3) & 1);           // + ks*2

    for (int kt = 0; kt < nk; kt++) {
        if (kt + 1 < nk) ld_stage(kt + 1, (kt + 1) & 1);
        if (kt + 1 < nk) asm volatile("cp.async.wait_group 1;" ::: "memory");
        else             asm volatile("cp.async.wait_group 0;" ::: "memory");
        __syncthreads();

        const uint32_t As = a_base + (uint32_t)(kt & 1) * FG_STAGE;
        const uint32_t Bs = b_base + (uint32_t)(kt & 1) * FG_STAGE;
#pragma unroll
        for (int ks = 0; ks < 2; ks++) {
            uint32_t afr[2][4], bfr[8][2];
#pragma unroll
            for (int mi = 0; mi < 2; mi++) {
                uint32_t ad = As + (a_row + mi * 16) * 80 + (a_chk + ks * 2) * 16;
                LDSM_X4(afr[mi][0], afr[mi][1], afr[mi][2], afr[mi][3], ad);
            }
#pragma unroll
            for (int a = 0; a < 4; a++) {
                uint32_t bd = Bs + (b_row + a * 16) * 80 + (b_chk + ks * 2) * 16;
                LDSM_X4(bfr[2 * a][0], bfr[2 * a][1], bfr[2 * a + 1][0], bfr[2 * a + 1][1], bd);
            }
#pragma unroll
            for (int mi = 0; mi < 2; mi++)
#pragma unroll
                for (int ni = 0; ni < 8; ni++)
                    mma_f16(acc[mi][ni], afr[mi], bfr[ni]);
        }
        __syncthreads();
    }

    // epilogue: c fragment = (row g / g+8, col 2t, 2t+1)
#pragma unroll
    for (int mi = 0; mi < 2; mi++) {
        int row0 = m0 + wm * 32 + mi * 16 + g;
#pragma unroll
        for (int ni = 0; ni < 8; ni++) {
            int col = n0 + wn * 64 + ni * 8 + 2 * t;
            if (col < Nb) {
                *(float2*)(Cb + (size_t)row0 * Nb + col) =
                    make_float2(acc[mi][ni][0] * alpha, acc[mi][ni][1] * alpha);
                *(float2*)(Cb + (size_t)(row0 + 8) * Nb + col) =
                    make_float2(acc[mi][ni][2] * alpha, acc[mi][ni][3] * alpha);
            }
        }
    }
}

// ---------------- 1x1 conv + PReLU ----------------
template<int CINT, int COUT>
__global__ void __launch_bounds__(256)
conv1x1_prelu(const float* __restrict__ in, const float* __restrict__ w,
              const float* __restrict__ bias, const float* __restrict__ a,
              float* __restrict__ out, int HW) {
    __shared__ float ws[COUT * CINT];
    for (int i = threadIdx.x; i < COUT * CINT; i += blockDim.x) ws[i] = w[i];
    __syncthreads();
    const float alpha = a[0];
    int idx = blockIdx.x * blockDim.x + threadIdx.x;
    int b = idx / HW, p = idx - b * HW;
    const float* inp = in + (size_t)b * CINT * HW + p;
    float acc[COUT];
#pragma unroll
    for (int o = 0; o < COUT; o++) acc[o] = bias[o];
    for (int c = 0; c < CINT; c++) {
        float v = inp[(size_t)c * HW];
#pragma unroll
        for (int o = 0; o < COUT; o++) acc[o] = fmaf(ws[o * CINT + c], v, acc[o]);
    }
    float* op = out + (size_t)b * COUT * HW + p;
#pragma unroll
    for (int o = 0; o < COUT; o++) {
        float v = acc[o];
        op[(size_t)o * HW] = (v >= 0.f) ? v : alpha * v;
    }
}

// ---------------- Q = im2col(match), zero-padded, fp16 ----------------
__global__ void im2col_q() {
    size_t idx = (size_t)blockIdx.x * 256 + threadIdx.x;
    int d = (int)(idx % DK);
    int q = (int)((idx / DK) % NQ);
    int b = (int)(idx / ((size_t)DK * NQ));
    int c = d / 9, kk = d % 9, ky = kk / 3, kx = kk % 3;
    int y = q / HIMG, x = q % HIMG;
    int yy = y + ky - 1, xx = x + kx - 1;
    float v = 0.f;
    if (yy >= 0 && yy < HIMG && xx >= 0 && xx < HIMG)
        v = g_match[(((size_t)b * CR + c) * HIMG + yy) * HIMG + xx];
    g_Q[idx] = __float2half_rn(v);
}

// ---------------- per-key inverse patch norms ----------------
__global__ void key_inv_norms() {
    int idx = blockIdx.x * 256 + threadIdx.x;
    int l = idx % NL, b = idx / NL;
    int ly = l / SIMG, lx = l % SIMG;
    const float* rb = g_ref + (size_t)b * CR * NL;
    float ss = 0.f;
    for (int c = 0; c < CR; c++)
        for (int ky = 0; ky < 3; ky++) {
            int yy = ly + ky - 1;
            if (yy < 0 || yy >= SIMG) continue;
            for (int kx = 0; kx < 3; kx++) {
                int xx = lx + kx - 1;
                if (xx < 0 || xx >= SIMG) continue;
                float v = rb[((size_t)c * SIMG + yy) * SIMG + xx];
                ss += v * v;
            }
        }
    g_invn[idx] = 1.f / fmaxf(sqrtf(ss), EPSF);
}

// ---------------- K matrix = normalized ref patches, fp16 ----------------
__global__ void build_km() {
    size_t idx = (size_t)blockIdx.x * 256 + threadIdx.x;
    int d = (int)(idx % DK);
    int l = (int)((idx / DK) % NL);
    int b = (int)(idx / ((size_t)DK * NL));
    int c = d / 9, kk = d % 9, ky = kk / 3, kx = kk % 3;
    int ly = l / SIMG, lx = l % SIMG;
    int yy = ly + ky - 1, xx = lx + kx - 1;
    float v = 0.f;
    if (yy >= 0 && yy < SIMG && xx >= 0 && xx < SIMG)
        v = g_ref[(((size_t)b * CR + c) * SIMG + yy) * SIMG + xx];
    g_Km[idx] = __float2half_rn(v * g_invn[b * NL + l]);
}

// ---------------- V matrix ([b][dv][l]) = embed patches, fp16 ----------------
__global__ void build_v() {
    size_t idx = (size_t)blockIdx.x * 256 + threadIdx.x;
    int l  = (int)(idx % NL);
    int dv = (int)((idx / NL) % DV);
    int b  = (int)(idx / ((size_t)NL * DV));
    int c = dv / 9, kk = dv % 9, ky = kk / 3, kx = kk % 3;
    int ly = l / SIMG, lx = l % SIMG;
    int yy = ly + ky - 1, xx = lx + kx - 1;
    float v = 0.f;
    if (yy >= 0 && yy < SIMG && xx >= 0 && xx < SIMG)
        v = g_embed[(((size_t)b * C64 + c) * SIMG + yy) * SIMG + xx];
    g_V[idx] = __float2half_rn(v);
}

// ---------------- row softmax over 2304 keys: fp32 S -> fp16 P ----------------
__global__ void __launch_bounds__(256)
softmax_rows() {
    const float* p = g_S + (size_t)blockIdx.x * NL;
    __half* po = g_P + (size_t)blockIdx.x * NL;
    const int t = threadIdx.x;
    float v[9];
    float m = -1e30f;
#pragma unroll
    for (int i = 0; i < 9; i++) { v[i] = p[t + i * 256]; m = fmaxf(m, v[i]); }
    __shared__ float red[256];
    red[t] = m; __syncthreads();
    for (int s = 128; s > 0; s >>= 1) { if (t < s) red[t] = fmaxf(red[t], red[t + s]); __syncthreads(); }
    m = red[0];
    __syncthreads();
    float sum = 0.f;
#pragma unroll
    for (int i = 0; i < 9; i++) { v[i] = expf(v[i] - m); sum += v[i]; }
    red[t] = sum; __syncthreads();
    for (int s = 128; s > 0; s >>= 1) { if (t < s) red[t] += red[t + s]; __syncthreads(); }
    float inv = 1.f / red[0];
#pragma unroll
    for (int i = 0; i < 9; i++) po[t + i * 256] = __float2half_rn(v[i] * inv);
}

// ---------------- gather epilogue (stride-2 transposed conv as gather) ----------------
__global__ void epilogue(float* __restrict__ out) {
    size_t idx = (size_t)blockIdx.x * 256 + threadIdx.x;
    int X = (int)(idx % OHW);
    int Y = (int)((idx / OHW) % OHW);
    int c = (int)((idx / ((size_t)OHW * OHW)) % C64);
    int b = (int)(idx / ((size_t)OHW * OHW * C64));

    int ys[2], kys[2], ny;
    if (Y & 1) { ny = 2; ys[0] = (Y - 1) >> 1; kys[0] = 2; ys[1] = (Y + 1) >> 1; kys[1] = 0; }
    else       { ny = 1; ys[0] = Y >> 1;       kys[0] = 1; }
    int xs[2], kxs[2], nx;
    if (X & 1) { nx = 2; xs[0] = (X - 1) >> 1; kxs[0] = 2; xs[1] = (X + 1) >> 1; kxs[1] = 0; }
    else       { nx = 1; xs[0] = X >> 1;       kxs[0] = 1; }

    const float* Ob = g_O + (size_t)b * NQ * DV;
    float s = 0.f;
    for (int iy = 0; iy < ny; iy++)
        for (int ix = 0; ix < nx; ix++) {
            int q = ys[iy] * HIMG + xs[ix];
            s += Ob[(size_t)q * DV + c * 9 + kys[iy] * 3 + kxs[ix]];
        }
    out[idx] = s * (1.0f / 6.0f);
}

// ---------------- launch ----------------
extern "C" void kernel_launch(void* const* d_in, const int* in_sizes, int n_in,
                              void* d_out, int out_size) {
    const float* input = (const float*)d_in[0];
    const float* small = (const float*)d_in[1];
    const float* w1 = (const float*)d_in[2];
    const float* b1 = (const float*)d_in[3];
    const float* a1 = (const float*)d_in[4];
    const float* w2 = (const float*)d_in[5];
    const float* b2 = (const float*)d_in[6];
    const float* a2 = (const float*)d_in[7];
    const float* wa = (const float*)d_in[8];
    const float* ba = (const float*)d_in[9];
    const float* aa = (const float*)d_in[10];
    float* out = (float*)d_out;

    float *p_match, *p_embed, *p_ref, *p_invn, *p_S, *p_O;
    __half *p_Q, *p_Km, *p_V, *p_P;
    cudaGetSymbolAddress((void**)&p_match, g_match);
    cudaGetSymbolAddress((void**)&p_embed, g_embed);
    cudaGetSymbolAddress((void**)&p_ref,   g_ref);
    cudaGetSymbolAddress((void**)&p_Q,     g_Q);
    cudaGetSymbolAddress((void**)&p_Km,    g_Km);
    cudaGetSymbolAddress((void**)&p_V,     g_V);
    cudaGetSymbolAddress((void**)&p_invn,  g_invn);
    cudaGetSymbolAddress((void**)&p_S,     g_S);
    cudaGetSymbolAddress((void**)&p_P,     g_P);
    cudaGetSymbolAddress((void**)&p_O,     g_O);

    // feature maps
    conv1x1_prelu<C64, CR><<<144, 256>>>(input, w1, b1, a1, p_match, NQ);
    conv1x1_prelu<C64, C64><<<36, 256>>>(small, wa, ba, aa, p_embed, NL);
    conv1x1_prelu<C64, CR><<<36, 256>>>(small, w2, b2, a2, p_ref, NL);

    // Q / K / V materialization (fp16)
    im2col_q<<<41472, 256>>>();
    key_inv_norms<<<36, 256>>>();
    build_km<<<10368, 256>>>();
    build_v<<<20736, 256>>>();

    // S = 10 * Q K^T   (fp16 tensor cores, fp32 accum)
    gemm_f16<<<dim3(18, 72, BATCH), 256>>>(p_Q, p_Km, p_S, DK, NL, SCALEF,
                                           (size_t)NQ * DK, (size_t)NL * DK, (size_t)NQ * NL);
    // softmax over keys -> fp16 P
    softmax_rows<<<BATCH * NQ, 256>>>();
    // O = P V   (fp16 tensor cores, fp32 accum)
    gemm_f16<<<dim3(5, 72, BATCH), 256>>>(p_P, p_V, p_O, NL, DV, 1.0f,
                                          (size_t)NQ * NL, (size_t)DV * NL, (size_t)NQ * DV);
    // gather into [4,64,191,191] with /6
    epilogue<<<36481, 256>>>(out);
}